// round 5
// baseline (speedup 1.0000x reference)
#include <cuda_runtime.h>
#include <cstdint>
#include <math.h>

#define T_TOK 4096
#define HDIM  2048
#define IDIM  768
#define NEXP  16
#define N13   (2*IDIM)          // 1536
#define NROWS (T_TOK*2)         // 8192 expanded rows (token, k)

// ---------------- scratch (__device__ globals) --------------------------------
__device__ int   g_mode_w13, g_mode_a13, g_mode_w2, g_mode_a2;
__device__ int   g_token_eidx[NROWS];
__device__ float g_token_wt[NROWS];
__device__ __align__(256) float g_xs2 [NROWS*HDIM];  // 64 MB
__device__ __align__(256) float g_gu  [NROWS*N13];   // 48 MB
__device__ __align__(256) float g_act [NROWS*IDIM];  // 24 MB
__device__ __align__(256) float g_down[NROWS*HDIM];  // 64 MB

// ---------------- dtype-delivery detection ------------------------------------
// mode 0: native 8-bit.  mode 1: widened to int32 (1 logical value / int32).
// mode 2: widened to float32.
__device__ int detect_mode(const void* p, int lo) {
    const int*   pi = (const int*)p;
    const float* pf = (const float*)p;
    bool i32 = true, f32 = true;
    for (int j = 0; j < 8; j++) {
        int v = pi[j];
        if (v < lo || v > 255) i32 = false;
        float f = pf[j];
        if (!(f >= (float)lo - 0.5f && f <= 255.5f && f == rintf(f))) f32 = false;
    }
    if (i32) return 1;
    if (f32) return 2;
    return 0;
}

__global__ void k_detect(const void* w13p, const void* a13q,
                         const void* w2p,  const void* a2q) {
    if (threadIdx.x == 0) {
        g_mode_w13 = detect_mode(w13p, 0);
        g_mode_a13 = detect_mode(a13q, 1);   // quantized alphas are >= ~25
        g_mode_w2  = detect_mode(w2p, 0);
        g_mode_a2  = detect_mode(a2q, 1);
    }
}

// signed int8 logical value
__device__ __forceinline__ int ldq(const void* p, long i, int mode) {
    if (mode == 1) return ((const int*)p)[i];
    if (mode == 2) return (int)((const float*)p)[i];
    return (int)((const int8_t*)p)[i];
}
// unsigned byte logical value
__device__ __forceinline__ uint32_t ldb(const void* p, long i, int mode) {
    if (mode == 1) return (uint32_t)((const int*)p)[i] & 0xFFu;
    if (mode == 2) return (uint32_t)(int)((const float*)p)[i] & 0xFFu;
    return (uint32_t)((const uint8_t*)p)[i];
}

// ---------------- router ------------------------------------------------------
__global__ void k_router(const float* __restrict__ logits) {
    int t = blockIdx.x * 256 + threadIdx.x;
    if (t >= T_TOK) return;
    float l[NEXP];
#pragma unroll
    for (int e = 0; e < NEXP; e++) l[e] = logits[t * NEXP + e];
    int i0 = 0; float b0 = l[0];
#pragma unroll
    for (int e = 1; e < NEXP; e++) if (l[e] > b0) { b0 = l[e]; i0 = e; }
    int i1 = -1; float b1 = -1e30f;
#pragma unroll
    for (int e = 0; e < NEXP; e++) if (e != i0 && l[e] > b1) { b1 = l[e]; i1 = e; }
    float w0 = 1.0f / (1.0f + expf(b1 - b0));   // renormalized top-2 softmax weight
    g_token_eidx[2*t]   = i0;
    g_token_eidx[2*t+1] = i1;
    g_token_wt[2*t]     = w0;
    g_token_wt[2*t+1]   = 1.0f - w0;
}

// xs2[r=2t+k][h] = x[t][h] * a13[e_r][h] * s13   (alpha folded on contraction dim)
__global__ void k_prescale(const float* __restrict__ x, const void* __restrict__ aq,
                           const float* __restrict__ asc) {
    int r = blockIdx.x;
    int t = r >> 1;
    int e = g_token_eidx[r];
    int mode = g_mode_a13;
    float sc = asc[0];
    const float* xr = x + (size_t)t * HDIM;
    float* o = g_xs2 + (size_t)r * HDIM;
    for (int j = threadIdx.x; j < HDIM; j += 256)
        o[j] = xr[j] * (float)ldq(aq, (long)e * HDIM + j, mode) * sc;
}

// ---------------- naive ternary GEMM (correct-by-construction) ----------------
// C[r][n] = sum_k A[r][k] * dec(B[e_r][n][k]); packed 4x2-bit/byte, elem j at bits 2j.
template <int WHICH>
__global__ __launch_bounds__(256) void k_sgemm(const void* __restrict__ Bp) {
    constexpr int K = (WHICH == 0) ? HDIM : IDIM;
    constexpr int N = (WHICH == 0) ? N13  : HDIM;
    const float* A = (WHICH == 0) ? g_xs2 : g_act;
    float*       C = (WHICH == 0) ? g_gu  : g_down;

    __shared__ float sa[K];
    int r = blockIdx.x;
    int e = g_token_eidx[r];
    int mode = (WHICH == 0) ? g_mode_w13 : g_mode_w2;
    const float* Ar = A + (size_t)r * K;
    for (int j = threadIdx.x; j < K; j += 256) sa[j] = Ar[j];
    __syncthreads();

    int n = blockIdx.y * 256 + threadIdx.x;          // N is a multiple of 256
    long rowbase = ((long)e * N + n) * (K / 4);      // in logical bytes
    float acc = 0.f;
    if (mode == 0) {
        const uint8_t* row = (const uint8_t*)Bp + rowbase;
        for (int kb = 0; kb < K / 4; kb += 4) {
            uint32_t p = *(const uint32_t*)(row + kb);   // 16 ternary values
#pragma unroll
            for (int j = 0; j < 16; j++) {
                int v = (int)((p >> (2 * j)) & 3u) - 1;
                acc = fmaf(sa[kb * 4 + j], (float)v, acc);
            }
        }
    } else {
        for (int kb = 0; kb < K / 4; kb++) {
            uint32_t b = ldb(Bp, rowbase + kb, mode);
#pragma unroll
            for (int j = 0; j < 4; j++) {
                int v = (int)((b >> (2 * j)) & 3u) - 1;
                acc = fmaf(sa[kb * 4 + j], (float)v, acc);
            }
        }
    }
    C[(size_t)r * N + n] = acc;
}

// act[r][i] = silu(gu[r][i]) * gu[r][I+i] * a2[e_r][i] * s2
__global__ void k_act2(const void* __restrict__ aq, const float* __restrict__ asc) {
    int r = blockIdx.x;
    int e = g_token_eidx[r];
    int mode = g_mode_a2;
    float sc = asc[0];
    const float* gr = g_gu + (size_t)r * N13;
    float* o = g_act + (size_t)r * IDIM;
    for (int j = threadIdx.x; j < IDIM; j += 256) {
        float gg = gr[j], uu = gr[IDIM + j];
        float s = gg / (1.0f + expf(-gg));
        o[j] = s * uu * (float)ldq(aq, (long)e * IDIM + j, mode) * sc;
    }
}

__global__ void k_combine(float* __restrict__ out) {
    int t = blockIdx.x;
    float w0 = g_token_wt[2*t], w1 = g_token_wt[2*t+1];
    const float* d0 = g_down + (size_t)(2*t)     * HDIM;
    const float* d1 = g_down + (size_t)(2*t + 1) * HDIM;
    float* o = out + (size_t)t * HDIM;
    for (int j = threadIdx.x; j < HDIM; j += 256)
        o[j] = w0 * d0[j] + w1 * d1[j];
}

// ---------------- launch ------------------------------------------------------
extern "C" void kernel_launch(void* const* d_in, const int* in_sizes, int n_in,
                              void* d_out, int out_size) {
    // Identify inputs by element count (all unique except the two scalars).
    const float* x      = nullptr;  // 8388608
    const float* logits = nullptr;  // 65536
    const void*  w13p   = nullptr;  // 12582912 logical bytes
    const void*  a13q   = nullptr;  // 32768
    const float* a13s   = nullptr;  // 1 (first scalar in order)
    const void*  w2p    = nullptr;  // 6291456
    const void*  a2q    = nullptr;  // 12288
    const float* a2s    = nullptr;  // 1 (second scalar in order)
    for (int i = 0; i < n_in; i++) {
        long sz = in_sizes[i];
        void* p = d_in[i];
        if      (sz == 8388608)  x      = (const float*)p;
        else if (sz == 65536)    logits = (const float*)p;
        else if (sz == 12582912) w13p   = p;
        else if (sz == 32768)    a13q   = p;
        else if (sz == 6291456)  w2p    = p;
        else if (sz == 12288)    a2q    = p;
        else if (sz == 1) { if (!a13s) a13s = (const float*)p; else a2s = (const float*)p; }
    }
    float* out = (float*)d_out;

    k_detect  <<<1, 32>>>(w13p, a13q, w2p, a2q);
    k_router  <<<T_TOK/256, 256>>>(logits);
    k_prescale<<<NROWS, 256>>>(x, a13q, a13s);
    k_sgemm<0><<<dim3(NROWS, N13/256), 256>>>(w13p);
    k_act2    <<<NROWS, 256>>>(a2q, a2s);
    k_sgemm<1><<<dim3(NROWS, HDIM/256), 256>>>(w2p);
    k_combine <<<T_TOK, 256>>>(out);
}

// round 7
// speedup vs baseline: 55.4211x; 55.4211x over previous
#include <cuda_runtime.h>
#include <cuda_fp16.h>
#include <cstdint>
#include <math.h>

#define T_TOK 4096
#define HDIM  2048
#define IDIM  768
#define NEXP  16
#define N13   (2*IDIM)          // 1536
#define MAXSLOTS 10496          // 8192 + 16*127 pad max = 10224
#define MAXTILES 96
#define GRID_TILES 80
#define W13_BYTES (NEXP*N13*(HDIM/4))   // 12582912
#define W2_BYTES  (NEXP*HDIM*(IDIM/4))  // 6291456

// ---------------- scratch (__device__ globals) --------------------------------
__device__ int   g_counts[NEXP];
__device__ int   g_cnt2[NEXP];
__device__ int   g_pad_off[NEXP+1];
__device__ int   g_tile_e[MAXTILES];
__device__ int   g_tile_m0[MAXTILES];
__device__ int   g_ntiles;
__device__ int   g_nslots;
__device__ int   g_assign_token[MAXSLOTS];
__device__ int   g_token_eidx[T_TOK*2];
__device__ int   g_token_slot[T_TOK*2];
__device__ float g_token_wt[T_TOK*2];
__device__ __align__(256) uint8_t g_w13[W13_BYTES];     // repacked native 2-bit
__device__ __align__(256) uint8_t g_w2 [W2_BYTES];
__device__ __align__(256) float   g_a13f[NEXP*HDIM];    // alpha * scale, fp32
__device__ __align__(256) float   g_a2f [NEXP*IDIM];
__device__ __align__(256) __half  g_xs [MAXSLOTS*HDIM];
__device__ __align__(256) float   g_gu [MAXSLOTS*N13];
__device__ __align__(256) __half  g_act[MAXSLOTS*IDIM];
__device__ __align__(256) float   g_down[MAXSLOTS*HDIM];

// ---------------- dtype-delivery detection + repack ---------------------------
// mode 0: native 8-bit.  mode 1: widened to int32.  mode 2: widened to float32.
__device__ __forceinline__ int detect_mode(const void* p, int lo) {
    const int*   pi = (const int*)p;
    const float* pf = (const float*)p;
    bool i32 = true, f32 = true;
    for (int j = 0; j < 8; j++) {
        int v = pi[j];
        if (v < lo || v > 255) i32 = false;
        float f = pf[j];
        if (!(f >= (float)lo - 0.5f && f <= 255.5f && f == rintf(f))) f32 = false;
    }
    if (i32) return 1;
    if (f32) return 2;
    return 0;
}
__device__ __forceinline__ uint32_t ldb(const void* p, long i, int mode) {
    if (mode == 1) return (uint32_t)((const int*)p)[i] & 0xFFu;
    if (mode == 2) return (uint32_t)(int)((const float*)p)[i] & 0xFFu;
    return (uint32_t)((const uint8_t*)p)[i];
}
__device__ __forceinline__ int ldq(const void* p, long i, int mode) {
    if (mode == 1) return ((const int*)p)[i];
    if (mode == 2) return (int)((const float*)p)[i];
    return (int)((const int8_t*)p)[i];
}

template <long NBYTES, int WHICH>
__global__ void k_repack_w(const void* __restrict__ src) {
    __shared__ int s_mode;
    if (threadIdx.x == 0) s_mode = detect_mode(src, 0);
    __syncthreads();
    int mode = s_mode;
    uint8_t* dst = (WHICH == 0) ? g_w13 : g_w2;
    long i = (long)blockIdx.x * 256 + threadIdx.x;
    if (i < NBYTES) dst[i] = (uint8_t)ldb(src, i, mode);
}

template <int N, int WHICH>
__global__ void k_repack_a(const void* __restrict__ src, const float* __restrict__ sc) {
    __shared__ int s_mode;
    if (threadIdx.x == 0) s_mode = detect_mode(src, 1);
    __syncthreads();
    float* dst = (WHICH == 0) ? g_a13f : g_a2f;
    float s = sc[0];
    int i = blockIdx.x * 256 + threadIdx.x;
    if (i < N) dst[i] = (float)ldq(src, i, s_mode) * s;
}

// ---------------- routing / dispatch ------------------------------------------
__global__ void k_init() {
    if (threadIdx.x < NEXP) { g_counts[threadIdx.x] = 0; g_cnt2[threadIdx.x] = 0; }
}

__global__ void k_router(const float* __restrict__ logits) {
    int t = blockIdx.x * 256 + threadIdx.x;
    if (t >= T_TOK) return;
    float l[NEXP];
#pragma unroll
    for (int e = 0; e < NEXP; e++) l[e] = logits[t * NEXP + e];
    int i0 = 0; float b0 = l[0];
#pragma unroll
    for (int e = 1; e < NEXP; e++) if (l[e] > b0) { b0 = l[e]; i0 = e; }
    int i1 = -1; float b1 = -1e30f;
#pragma unroll
    for (int e = 0; e < NEXP; e++) if (e != i0 && l[e] > b1) { b1 = l[e]; i1 = e; }
    float w0 = 1.0f / (1.0f + expf(b1 - b0));
    g_token_eidx[2*t]   = i0;
    g_token_eidx[2*t+1] = i1;
    g_token_wt[2*t]     = w0;
    g_token_wt[2*t+1]   = 1.0f - w0;
    atomicAdd(&g_counts[i0], 1);
    atomicAdd(&g_counts[i1], 1);
}

__global__ void k_scan() {
    if (threadIdx.x != 0) return;
    int off = 0, tiles = 0;
    for (int e = 0; e < NEXP; e++) {
        g_pad_off[e] = off;
        int nt = (g_counts[e] + 127) >> 7;
        for (int j = 0; j < nt; j++) { g_tile_e[tiles] = e; g_tile_m0[tiles] = off + (j << 7); tiles++; }
        off += nt << 7;
    }
    g_pad_off[NEXP] = off;
    g_ntiles = tiles;
    g_nslots = off;
}

__global__ void k_assign() {
    int t = blockIdx.x * 256 + threadIdx.x;
    if (t >= T_TOK) return;
    for (int k = 0; k < 2; k++) {
        int e = g_token_eidx[2*t+k];
        int r = atomicAdd(&g_cnt2[e], 1);
        int slot = g_pad_off[e] + r;
        g_assign_token[slot] = t;
        g_token_slot[2*t+k]  = slot;
    }
}

__device__ __forceinline__ int slot_expert(int slot) {
    int e = 0;
    while (e < NEXP-1 && g_pad_off[e+1] <= slot) e++;
    return e;
}

// xs[slot,h] = fp16( x[t,h] * a13f[e,h] ); pad rows -> 0
__global__ void k_xs(const float* __restrict__ x) {
    int slot = blockIdx.x;
    if (slot >= g_nslots) return;
    int e = slot_expert(slot);
    __half* o = g_xs + (size_t)slot * HDIM;
    if (slot - g_pad_off[e] >= g_counts[e]) {
        for (int j = threadIdx.x; j < HDIM; j += 256) o[j] = __float2half(0.f);
        return;
    }
    int t = g_assign_token[slot];
    const float* xr = x + (size_t)t * HDIM;
    const float* ar = g_a13f + (size_t)e * HDIM;
    for (int j = threadIdx.x; j < HDIM; j += 256)
        o[j] = __float2half(xr[j] * ar[j]);
}

// act[slot,i] = fp16( silu(gu[slot,i]) * gu[slot,I+i] * a2f[e,i] )
__global__ void k_act(int dummy) {
    int slot = blockIdx.x;
    if (slot >= g_nslots) return;
    int e = slot_expert(slot);
    __half* o = g_act + (size_t)slot * IDIM;
    if (slot - g_pad_off[e] >= g_counts[e]) {
        for (int j = threadIdx.x; j < IDIM; j += 256) o[j] = __float2half(0.f);
        return;
    }
    const float* gr = g_gu + (size_t)slot * N13;
    const float* ar = g_a2f + (size_t)e * IDIM;
    for (int j = threadIdx.x; j < IDIM; j += 256) {
        float gg = gr[j], uu = gr[IDIM + j];
        float s = gg / (1.0f + expf(-gg));
        o[j] = __float2half(s * uu * ar[j]);
    }
}

__global__ void k_combine(float* __restrict__ out) {
    int t = blockIdx.x;
    int s0 = g_token_slot[2*t], s1 = g_token_slot[2*t+1];
    float w0 = g_token_wt[2*t], w1 = g_token_wt[2*t+1];
    const float* d0 = g_down + (size_t)s0 * HDIM;
    const float* d1 = g_down + (size_t)s1 * HDIM;
    float* o = out + (size_t)t * HDIM;
    for (int j = threadIdx.x; j < HDIM; j += 256)
        o[j] = w0 * d0[j] + w1 * d1[j];
}

// ---------------- GEMM: fp16 A x ternary-2bit B -> fp32 C --------------------
// BM=128 BN=128 BK=32, 256 threads (8 warps, 4(M)x2(N)), warp tile 32x64,
// mma.sync.m16n8k16, fragments via direct LDS (validated bit-equal vs naive).
__device__ __forceinline__ void mma16816(float* c, const uint32_t* a, const uint32_t* b) {
    asm volatile("mma.sync.aligned.m16n8k16.row.col.f32.f16.f16.f32 "
                 "{%0,%1,%2,%3},{%4,%5,%6,%7},{%8,%9},{%0,%1,%2,%3};"
                 : "+f"(c[0]), "+f"(c[1]), "+f"(c[2]), "+f"(c[3])
                 : "r"(a[0]), "r"(a[1]), "r"(a[2]), "r"(a[3]), "r"(b[0]), "r"(b[1]));
}

template <int WHICH>  // 0: xs @ w13^T -> gu.  1: act @ w2^T -> down.
__global__ __launch_bounds__(256) void k_gemm() {
    constexpr int K = (WHICH == 0) ? HDIM : IDIM;
    constexpr int N = (WHICH == 0) ? N13  : HDIM;
    constexpr int KB = K / 4;
    const __half*  A  = (WHICH == 0) ? g_xs  : g_act;
    float*         C  = (WHICH == 0) ? g_gu  : g_down;
    const uint8_t* Bp = (WHICH == 0) ? g_w13 : g_w2;

    __shared__ __half sA[128][40];
    __shared__ __half sB[128][40];
    __shared__ uint2  s_lut[256];

    int bx = blockIdx.x;
    if (bx >= g_ntiles) return;
    int e  = g_tile_e[bx];
    int m0 = g_tile_m0[bx];
    int n0 = blockIdx.y * 128;
    const uint8_t* Be = Bp + (size_t)e * N * KB;

    int tid = threadIdx.x;
    {   // LUT: byte -> 4 fp16 in {-1,0,+1}
        int b = tid;
        unsigned short h[4];
#pragma unroll
        for (int j = 0; j < 4; j++) {
            int v = ((b >> (2*j)) & 3) - 1;
            h[j] = (v == 0) ? 0x0000 : ((v == 1) ? 0x3C00 : 0xBC00);
        }
        uint2 val;
        val.x = (uint32_t)h[0] | ((uint32_t)h[1] << 16);
        val.y = (uint32_t)h[2] | ((uint32_t)h[3] << 16);
        s_lut[tid] = val;
    }

    int w = tid >> 5, lane = tid & 31;
    int wm = w & 3, wn = w >> 2;
    int gid = lane >> 2, tig = lane & 3;

    float c[2][8][4] = {};
    __syncthreads();

    for (int k0 = 0; k0 < K; k0 += 32) {
#pragma unroll
        for (int it = 0; it < 2; it++) {
            int idx = tid + it * 256;
            int r = idx >> 2, cc = idx & 3;
            *(uint4*)(&sA[r][cc * 8]) =
                *(const uint4*)(A + (size_t)(m0 + r) * K + k0 + cc * 8);
        }
        {
            int r = tid >> 1, sel = tid & 1;
            uint32_t p = *(const uint32_t*)(Be + (size_t)(n0 + r) * KB + (k0 >> 2) + sel * 4);
#pragma unroll
            for (int j = 0; j < 4; j++)
                *(uint2*)(&sB[r][sel * 16 + j * 4]) = s_lut[(p >> (8 * j)) & 0xFF];
        }
        __syncthreads();

#pragma unroll
        for (int kk = 0; kk < 32; kk += 16) {
            uint32_t af[2][4], bf[8][2];
#pragma unroll
            for (int mt = 0; mt < 2; mt++) {
                int r = wm * 32 + mt * 16 + gid;
                af[mt][0] = *(const uint32_t*)(&sA[r    ][kk +     2 * tig]);
                af[mt][1] = *(const uint32_t*)(&sA[r + 8][kk +     2 * tig]);
                af[mt][2] = *(const uint32_t*)(&sA[r    ][kk + 8 + 2 * tig]);
                af[mt][3] = *(const uint32_t*)(&sA[r + 8][kk + 8 + 2 * tig]);
            }
#pragma unroll
            for (int ns = 0; ns < 8; ns++) {
                int r = wn * 64 + ns * 8 + gid;
                bf[ns][0] = *(const uint32_t*)(&sB[r][kk +     2 * tig]);
                bf[ns][1] = *(const uint32_t*)(&sB[r][kk + 8 + 2 * tig]);
            }
#pragma unroll
            for (int mt = 0; mt < 2; mt++)
#pragma unroll
                for (int ns = 0; ns < 8; ns++)
                    mma16816(c[mt][ns], af[mt], bf[ns]);
        }
        __syncthreads();
    }

#pragma unroll
    for (int mt = 0; mt < 2; mt++)
#pragma unroll
        for (int ns = 0; ns < 8; ns++) {
            int row = m0 + wm * 32 + mt * 16 + gid;
            int col = n0 + wn * 64 + ns * 8 + tig * 2;
            *(float2*)(C + (size_t)row * N + col)       = make_float2(c[mt][ns][0], c[mt][ns][1]);
            *(float2*)(C + (size_t)(row + 8) * N + col) = make_float2(c[mt][ns][2], c[mt][ns][3]);
        }
}

// ---------------- launch ------------------------------------------------------
extern "C" void kernel_launch(void* const* d_in, const int* in_sizes, int n_in,
                              void* d_out, int out_size) {
    const float* x      = nullptr;
    const float* logits = nullptr;
    const void*  w13p   = nullptr;
    const void*  a13q   = nullptr;
    const float* a13s   = nullptr;
    const void*  w2p    = nullptr;
    const void*  a2q    = nullptr;
    const float* a2s    = nullptr;
    for (int i = 0; i < n_in; i++) {
        long sz = in_sizes[i];
        void* p = d_in[i];
        if      (sz == 8388608)  x      = (const float*)p;
        else if (sz == 65536)    logits = (const float*)p;
        else if (sz == 12582912) w13p   = p;
        else if (sz == 32768)    a13q   = p;
        else if (sz == 6291456)  w2p    = p;
        else if (sz == 12288)    a2q    = p;
        else if (sz == 1) { if (!a13s) a13s = (const float*)p; else a2s = (const float*)p; }
    }
    float* out = (float*)d_out;

    k_repack_w<W13_BYTES,0><<<(W13_BYTES+255)/256, 256>>>(w13p);
    k_repack_w<W2_BYTES, 1><<<(W2_BYTES +255)/256, 256>>>(w2p);
    k_repack_a<NEXP*HDIM,0><<<(NEXP*HDIM+255)/256, 256>>>(a13q, a13s);
    k_repack_a<NEXP*IDIM,1><<<(NEXP*IDIM+255)/256, 256>>>(a2q, a2s);
    k_init  <<<1, 32>>>();
    k_router<<<T_TOK/256, 256>>>(logits);
    k_scan  <<<1, 32>>>();
    k_assign<<<T_TOK/256, 256>>>();
    k_xs    <<<10240, 256>>>(x);
    k_gemm<0><<<dim3(GRID_TILES, N13 / 128), 256>>>();
    k_act   <<<10240, 256>>>(0);
    k_gemm<1><<<dim3(GRID_TILES, HDIM / 128), 256>>>();
    k_combine<<<T_TOK, 256>>>(out);
}

// round 11
// speedup vs baseline: 66.0805x; 1.1923x over previous
#include <cuda_runtime.h>
#include <cuda_fp16.h>
#include <cstdint>
#include <math.h>

#define T_TOK 4096
#define HDIM  2048
#define IDIM  768
#define NEXP  16
#define N13   (2*IDIM)          // 1536
#define MAXSLOTS 10496
#define MAXTILES 96
#define GRID_TILES 80
#define W13_BYTES (NEXP*N13*(HDIM/4))   // 12582912
#define W2_BYTES  (NEXP*HDIM*(IDIM/4))  // 6291456

// ---------------- scratch (__device__ globals) --------------------------------
__device__ int   g_counts[NEXP];
__device__ int   g_cnt2[NEXP];
__device__ int   g_pad_off[NEXP+1];
__device__ int   g_tile_e[MAXTILES];
__device__ int   g_tile_m0[MAXTILES];
__device__ int   g_ntiles;
__device__ int   g_nslots;
__device__ int   g_assign_token[MAXSLOTS];
__device__ int   g_token_eidx[T_TOK*2];
__device__ int   g_token_slot[T_TOK*2];
__device__ float g_token_wt[T_TOK*2];
__device__ __align__(256) uint8_t g_w13[W13_BYTES];
__device__ __align__(256) uint8_t g_w2 [W2_BYTES];
__device__ __align__(256) float   g_a13f[NEXP*HDIM];
__device__ __align__(256) float   g_a2f [NEXP*IDIM];
__device__ __align__(256) __half  g_xs [MAXSLOTS*HDIM];
__device__ __align__(256) float   g_gu [MAXSLOTS*N13];
__device__ __align__(256) __half  g_act[MAXSLOTS*IDIM];
__device__ __align__(256) float   g_down[MAXSLOTS*HDIM];

// ---------------- dtype-delivery detection + repack ---------------------------
__device__ __forceinline__ int detect_mode(const void* p, int lo) {
    const int*   pi = (const int*)p;
    const float* pf = (const float*)p;
    bool i32 = true, f32 = true;
    for (int j = 0; j < 8; j++) {
        int v = pi[j];
        if (v < lo || v > 255) i32 = false;
        float f = pf[j];
        if (!(f >= (float)lo - 0.5f && f <= 255.5f && f == rintf(f))) f32 = false;
    }
    if (i32) return 1;
    if (f32) return 2;
    return 0;
}
__device__ __forceinline__ uint32_t ldb(const void* p, long i, int mode) {
    if (mode == 1) return (uint32_t)((const int*)p)[i] & 0xFFu;
    if (mode == 2) return (uint32_t)(int)((const float*)p)[i] & 0xFFu;
    return (uint32_t)((const uint8_t*)p)[i];
}
__device__ __forceinline__ int ldq(const void* p, long i, int mode) {
    if (mode == 1) return ((const int*)p)[i];
    if (mode == 2) return (int)((const float*)p)[i];
    return (int)((const int8_t*)p)[i];
}

template <long NBYTES, int WHICH>
__global__ void k_repack_w(const void* __restrict__ src) {
    __shared__ int s_mode;
    if (threadIdx.x == 0) s_mode = detect_mode(src, 0);
    __syncthreads();
    int mode = s_mode;
    uint8_t* dst = (WHICH == 0) ? g_w13 : g_w2;
    long i = (long)blockIdx.x * 256 + threadIdx.x;
    if (i < NBYTES) dst[i] = (uint8_t)ldb(src, i, mode);
}

template <int N, int WHICH>
__global__ void k_repack_a(const void* __restrict__ src, const float* __restrict__ sc) {
    __shared__ int s_mode;
    if (threadIdx.x == 0) s_mode = detect_mode(src, 1);
    __syncthreads();
    float* dst = (WHICH == 0) ? g_a13f : g_a2f;
    float s = sc[0];
    int i = blockIdx.x * 256 + threadIdx.x;
    if (i < N) dst[i] = (float)ldq(src, i, s_mode) * s;
}

// ---------------- routing / dispatch ------------------------------------------
__global__ void k_init() {
    if (threadIdx.x < NEXP) { g_counts[threadIdx.x] = 0; g_cnt2[threadIdx.x] = 0; }
}

__global__ void k_router(const float* __restrict__ logits) {
    int t = blockIdx.x * 256 + threadIdx.x;
    if (t >= T_TOK) return;
    float l[NEXP];
#pragma unroll
    for (int e = 0; e < NEXP; e++) l[e] = logits[t * NEXP + e];
    int i0 = 0; float b0 = l[0];
#pragma unroll
    for (int e = 1; e < NEXP; e++) if (l[e] > b0) { b0 = l[e]; i0 = e; }
    int i1 = -1; float b1 = -1e30f;
#pragma unroll
    for (int e = 0; e < NEXP; e++) if (e != i0 && l[e] > b1) { b1 = l[e]; i1 = e; }
    float w0 = 1.0f / (1.0f + expf(b1 - b0));
    g_token_eidx[2*t]   = i0;
    g_token_eidx[2*t+1] = i1;
    g_token_wt[2*t]     = w0;
    g_token_wt[2*t+1]   = 1.0f - w0;
    atomicAdd(&g_counts[i0], 1);
    atomicAdd(&g_counts[i1], 1);
}

__global__ void k_scan() {
    if (threadIdx.x != 0) return;
    int off = 0, tiles = 0;
    for (int e = 0; e < NEXP; e++) {
        g_pad_off[e] = off;
        int nt = (g_counts[e] + 127) >> 7;
        for (int j = 0; j < nt; j++) { g_tile_e[tiles] = e; g_tile_m0[tiles] = off + (j << 7); tiles++; }
        off += nt << 7;
    }
    g_pad_off[NEXP] = off;
    g_ntiles = tiles;
    g_nslots = off;
}

__global__ void k_assign() {
    int t = blockIdx.x * 256 + threadIdx.x;
    if (t >= T_TOK) return;
    for (int k = 0; k < 2; k++) {
        int e = g_token_eidx[2*t+k];
        int r = atomicAdd(&g_cnt2[e], 1);
        int slot = g_pad_off[e] + r;
        g_assign_token[slot] = t;
        g_token_slot[2*t+k]  = slot;
    }
}

__device__ __forceinline__ int slot_expert(int slot) {
    int e = 0;
    while (e < NEXP-1 && g_pad_off[e+1] <= slot) e++;
    return e;
}

__global__ void k_xs(const float* __restrict__ x) {
    int slot = blockIdx.x;
    if (slot >= g_nslots) return;
    int e = slot_expert(slot);
    __half* o = g_xs + (size_t)slot * HDIM;
    if (slot - g_pad_off[e] >= g_counts[e]) {
        for (int j = threadIdx.x; j < HDIM; j += 256) o[j] = __float2half(0.f);
        return;
    }
    int t = g_assign_token[slot];
    const float* xr = x + (size_t)t * HDIM;
    const float* ar = g_a13f + (size_t)e * HDIM;
    for (int j = threadIdx.x; j < HDIM; j += 256)
        o[j] = __float2half(xr[j] * ar[j]);
}

__global__ void k_act(int dummy) {
    int slot = blockIdx.x;
    if (slot >= g_nslots) return;
    int e = slot_expert(slot);
    __half* o = g_act + (size_t)slot * IDIM;
    if (slot - g_pad_off[e] >= g_counts[e]) {
        for (int j = threadIdx.x; j < IDIM; j += 256) o[j] = __float2half(0.f);
        return;
    }
    const float* gr = g_gu + (size_t)slot * N13;
    const float* ar = g_a2f + (size_t)e * IDIM;
    for (int j = threadIdx.x; j < IDIM; j += 256) {
        float gg = gr[j], uu = gr[IDIM + j];
        float s = gg / (1.0f + expf(-gg));
        o[j] = __float2half(s * uu * ar[j]);
    }
}

__global__ void k_combine(float* __restrict__ out) {
    int t = blockIdx.x;
    int s0 = g_token_slot[2*t], s1 = g_token_slot[2*t+1];
    float w0 = g_token_wt[2*t], w1 = g_token_wt[2*t+1];
    const float* d0 = g_down + (size_t)s0 * HDIM;
    const float* d1 = g_down + (size_t)s1 * HDIM;
    float* o = out + (size_t)t * HDIM;
    for (int j = threadIdx.x; j < HDIM; j += 256)
        o[j] = w0 * d0[j] + w1 * d1[j];
}

// ---------------- GEMM: fp16 A x ternary-2bit B -> fp32 C --------------------
// BM=128 BN=128 BK=32, double-buffered SMEM, cp.async A loads, ldmatrix
// fragments (validated byte-equal to direct-LDS in R1/R2), one barrier/stage.
__device__ __forceinline__ void ldsm4(uint32_t& r0, uint32_t& r1, uint32_t& r2, uint32_t& r3,
                                      const void* p) {
    uint32_t a = (uint32_t)__cvta_generic_to_shared(p);
    asm volatile("ldmatrix.sync.aligned.m8n8.x4.shared.b16 {%0,%1,%2,%3},[%4];"
                 : "=r"(r0), "=r"(r1), "=r"(r2), "=r"(r3) : "r"(a));
}
__device__ __forceinline__ void mma16816(float* c, const uint32_t* a, const uint32_t* b) {
    asm volatile("mma.sync.aligned.m16n8k16.row.col.f32.f16.f16.f32 "
                 "{%0,%1,%2,%3},{%4,%5,%6,%7},{%8,%9},{%0,%1,%2,%3};"
                 : "+f"(c[0]), "+f"(c[1]), "+f"(c[2]), "+f"(c[3])
                 : "r"(a[0]), "r"(a[1]), "r"(a[2]), "r"(a[3]), "r"(b[0]), "r"(b[1]));
}

template <int WHICH>  // 0: xs @ w13^T -> gu.  1: act @ w2^T -> down.
__global__ __launch_bounds__(256, 2) void k_gemm() {
    constexpr int K = (WHICH == 0) ? HDIM : IDIM;
    constexpr int N = (WHICH == 0) ? N13  : HDIM;
    constexpr int KB = K / 4;
    constexpr int S  = K / 32;
    const __half*  A  = (WHICH == 0) ? g_xs  : g_act;
    float*         C  = (WHICH == 0) ? g_gu  : g_down;
    const uint8_t* Bp = (WHICH == 0) ? g_w13 : g_w2;

    __shared__ __half sA[2][128][40];
    __shared__ __half sB[2][128][40];
    __shared__ uint2  s_lut[256];

    int bx = blockIdx.x;
    if (bx >= g_ntiles) return;
    int e  = g_tile_e[bx];
    int m0 = g_tile_m0[bx];
    int n0 = blockIdx.y * 128;
    const uint8_t* Be = Bp + (size_t)e * N * KB;

    int tid = threadIdx.x;
    {   // LUT: byte -> 4 fp16 in {-1,0,+1}
        int b = tid;
        unsigned short h[4];
#pragma unroll
        for (int j = 0; j < 4; j++) {
            int v = ((b >> (2*j)) & 3) - 1;
            h[j] = (v == 0) ? 0x0000 : ((v == 1) ? 0x3C00 : 0xBC00);
        }
        uint2 val;
        val.x = (uint32_t)h[0] | ((uint32_t)h[1] << 16);
        val.y = (uint32_t)h[2] | ((uint32_t)h[3] << 16);
        s_lut[tid] = val;
    }

    int w = tid >> 5, lane = tid & 31;
    int wm = w & 3, wn = w >> 2;
    int gid = lane >> 2, tig = lane & 3;
    int aRow = (lane & 7) + ((lane >> 3) & 1) * 8;   // A tiles: (m,k0)(m+8,k0)(m,k8)(m+8,k8)
    int aCol = ((lane >> 4) & 1) * 8;
    int bRow = (lane & 7) + ((lane >> 4) & 1) * 8;   // B tiles: (n,k0)(n,k8)(n+8,k0)(n+8,k8)
    int bCol = ((lane >> 3) & 1) * 8;

    int ar0 = tid >> 2, ac0 = tid & 3;               // A-tile cp.async: 2 chunks/thread
    int br  = tid >> 1, bsel = tid & 1;              // B packed: 4 bytes/thread
    const __half* Abase = A + (size_t)(m0) * K;

    uint32_t pk = 0;

    // prologue: stage 0 in flight
    {
#pragma unroll
        for (int i = 0; i < 2; i++) {
            int r = ar0 + i * 64;
            uint32_t dst = (uint32_t)__cvta_generic_to_shared(&sA[0][r][ac0 * 8]);
            const void* src = Abase + (size_t)r * K + ac0 * 8;
            asm volatile("cp.async.cg.shared.global [%0], [%1], 16;" :: "r"(dst), "l"(src));
        }
        asm volatile("cp.async.commit_group;");
        pk = *(const uint32_t*)(Be + (size_t)(n0 + br) * KB + bsel * 4);
    }
    __syncthreads();   // LUT visible
    {   // decode B stage 0
#pragma unroll
        for (int j = 0; j < 4; j++)
            *(uint2*)(&sB[0][br][bsel * 16 + j * 4]) = s_lut[(pk >> (8 * j)) & 0xFF];
    }
    asm volatile("cp.async.wait_group 0;");
    __syncthreads();   // stage 0 ready

    float c[2][8][4] = {};

    for (int s = 0; s < S; s++) {
        int cur = s & 1, nxt = cur ^ 1;
        if (s + 1 < S) {
            int k0 = (s + 1) * 32;
#pragma unroll
            for (int i = 0; i < 2; i++) {
                int r = ar0 + i * 64;
                uint32_t dst = (uint32_t)__cvta_generic_to_shared(&sA[nxt][r][ac0 * 8]);
                const void* src = Abase + (size_t)r * K + k0 + ac0 * 8;
                asm volatile("cp.async.cg.shared.global [%0], [%1], 16;" :: "r"(dst), "l"(src));
            }
            asm volatile("cp.async.commit_group;");
            pk = *(const uint32_t*)(Be + (size_t)(n0 + br) * KB + (k0 >> 2) + bsel * 4);
        }

#pragma unroll
        for (int kk = 0; kk < 32; kk += 16) {
            uint32_t af[2][4], bf[8][2];
#pragma unroll
            for (int mt = 0; mt < 2; mt++)
                ldsm4(af[mt][0], af[mt][1], af[mt][2], af[mt][3],
                      &sA[cur][wm * 32 + mt * 16 + aRow][kk + aCol]);
#pragma unroll
            for (int np = 0; np < 4; np++) {
                uint32_t r0, r1, r2, r3;
                ldsm4(r0, r1, r2, r3, &sB[cur][wn * 64 + np * 16 + bRow][kk + bCol]);
                bf[2*np][0]   = r0; bf[2*np][1]   = r1;
                bf[2*np+1][0] = r2; bf[2*np+1][1] = r3;
            }
#pragma unroll
            for (int mt = 0; mt < 2; mt++)
#pragma unroll
                for (int ns = 0; ns < 8; ns++)
                    mma16816(c[mt][ns], af[mt], bf[ns]);
        }

        if (s + 1 < S) {
            asm volatile("cp.async.wait_group 0;");
#pragma unroll
            for (int j = 0; j < 4; j++)
                *(uint2*)(&sB[nxt][br][bsel * 16 + j * 4]) = s_lut[(pk >> (8 * j)) & 0xFF];
        }
        __syncthreads();
    }

#pragma unroll
    for (int mt = 0; mt < 2; mt++)
#pragma unroll
        for (int ns = 0; ns < 8; ns++) {
            int row = m0 + wm * 32 + mt * 16 + gid;
            int col = n0 + wn * 64 + ns * 8 + tig * 2;
            *(float2*)(C + (size_t)row * N + col)       = make_float2(c[mt][ns][0], c[mt][ns][1]);
            *(float2*)(C + (size_t)(row + 8) * N + col) = make_float2(c[mt][ns][2], c[mt][ns][3]);
        }
}

// ---------------- launch ------------------------------------------------------
extern "C" void kernel_launch(void* const* d_in, const int* in_sizes, int n_in,
                              void* d_out, int out_size) {
    const float* x      = nullptr;
    const float* logits = nullptr;
    const void*  w13p   = nullptr;
    const void*  a13q   = nullptr;
    const float* a13s   = nullptr;
    const void*  w2p    = nullptr;
    const void*  a2q    = nullptr;
    const float* a2s    = nullptr;
    for (int i = 0; i < n_in; i++) {
        long sz = in_sizes[i];
        void* p = d_in[i];
        if      (sz == 8388608)  x      = (const float*)p;
        else if (sz == 65536)    logits = (const float*)p;
        else if (sz == 12582912) w13p   = p;
        else if (sz == 32768)    a13q   = p;
        else if (sz == 6291456)  w2p    = p;
        else if (sz == 12288)    a2q    = p;
        else if (sz == 1) { if (!a13s) a13s = (const float*)p; else a2s = (const float*)p; }
    }
    float* out = (float*)d_out;

    k_repack_w<W13_BYTES,0><<<(W13_BYTES+255)/256, 256>>>(w13p);
    k_repack_w<W2_BYTES, 1><<<(W2_BYTES +255)/256, 256>>>(w2p);
    k_repack_a<NEXP*HDIM,0><<<(NEXP*HDIM+255)/256, 256>>>(a13q, a13s);
    k_repack_a<NEXP*IDIM,1><<<(NEXP*IDIM+255)/256, 256>>>(a2q, a2s);
    k_init  <<<1, 32>>>();
    k_router<<<T_TOK/256, 256>>>(logits);
    k_scan  <<<1, 32>>>();
    k_assign<<<T_TOK/256, 256>>>();
    k_xs    <<<10240, 256>>>(x);
    k_gemm<0><<<dim3(GRID_TILES, N13 / 128), 256>>>();
    k_act   <<<10240, 256>>>(0);
    k_gemm<1><<<dim3(GRID_TILES, HDIM / 128), 256>>>();
    k_combine<<<T_TOK, 256>>>(out);
}

// round 13
// speedup vs baseline: 66.2808x; 1.0030x over previous
#include <cuda_runtime.h>
#include <cuda_fp16.h>
#include <cstdint>
#include <math.h>

#define T_TOK 4096
#define HDIM  2048
#define IDIM  768
#define NEXP  16
#define N13   (2*IDIM)          // 1536
#define MAXSLOTS 10496
#define MAXTILES 96
#define GRID_TILES 80
#define W13_BYTES (NEXP*N13*(HDIM/4))   // 12582912
#define W2_BYTES  (NEXP*HDIM*(IDIM/4))  // 6291456

// ---------------- scratch (__device__ globals) --------------------------------
__device__ int   g_pad_off[NEXP+1];
__device__ int   g_tile_e[MAXTILES];
__device__ int   g_tile_m0[MAXTILES];
__device__ int   g_ntiles;
__device__ int   g_nslots;
__device__ int   g_token_eidx[T_TOK*2];
__device__ int   g_token_slot[T_TOK*2];
__device__ float g_token_wt[T_TOK*2];
__device__ __align__(256) uint8_t g_w13[W13_BYTES];   // interleaved: row 2j=gate_j, 2j+1=up_j
__device__ __align__(256) uint8_t g_w2 [W2_BYTES];
__device__ __align__(256) float   g_a13f[NEXP*HDIM];
__device__ __align__(256) float   g_a2f [NEXP*IDIM];
__device__ __align__(256) __half  g_xs [MAXSLOTS*HDIM];
__device__ __align__(256) __half  g_act[MAXSLOTS*IDIM];
__device__ __align__(256) float   g_down[MAXSLOTS*HDIM];

// ---------------- dtype-delivery detection ------------------------------------
__device__ __forceinline__ int detect_mode(const void* p, int lo) {
    const int*   pi = (const int*)p;
    const float* pf = (const float*)p;
    bool i32 = true, f32 = true;
    for (int j = 0; j < 8; j++) {
        int v = pi[j];
        if (v < lo || v > 255) i32 = false;
        float f = pf[j];
        if (!(f >= (float)lo - 0.5f && f <= 255.5f && f == rintf(f))) f32 = false;
    }
    if (i32) return 1;
    if (f32) return 2;
    return 0;
}
__device__ __forceinline__ uint32_t ldb(const void* p, long i, int mode) {
    if (mode == 1) return (uint32_t)((const int*)p)[i] & 0xFFu;
    if (mode == 2) return (uint32_t)(int)((const float*)p)[i] & 0xFFu;
    return (uint32_t)((const uint8_t*)p)[i];
}
__device__ __forceinline__ int ldq(const void* p, long i, int mode) {
    if (mode == 1) return ((const int*)p)[i];
    if (mode == 2) return (int)((const float*)p)[i];
    return (int)((const int8_t*)p)[i];
}

// ---------------- fused repack (+ g_xs zeroing) --------------------------------
#define RW13_BLKS (W13_BYTES/256)     // 49152
#define RW2_BLKS  (W2_BYTES/256)      // 24576
#define RA13_BLKS ((NEXP*HDIM)/256)   // 128
#define RA2_BLKS  ((NEXP*IDIM)/256)   // 48
#define ZX_BLKS   MAXSLOTS            // one block per g_xs row
#define REPACK_BLKS (RW13_BLKS + RW2_BLKS + RA13_BLKS + RA2_BLKS + ZX_BLKS)

__global__ void k_repack(const void* __restrict__ w13p, const void* __restrict__ w2p,
                         const void* __restrict__ a13q, const float* __restrict__ a13s,
                         const void* __restrict__ a2q,  const float* __restrict__ a2s) {
    __shared__ int s_mode;
    int bid = blockIdx.x, tid = threadIdx.x;
    if (bid < RW13_BLKS) {
        if (tid == 0) s_mode = detect_mode(w13p, 0);
        __syncthreads();
        long i = (long)bid * 256 + tid;              // dst byte index (interleaved rows)
        int e   = (int)(i / (N13 * (HDIM/4)));
        int rem = (int)(i % (N13 * (HDIM/4)));
        int rp  = rem / (HDIM/4);
        int kb  = rem % (HDIM/4);
        int r   = (rp & 1) ? (IDIM + (rp >> 1)) : (rp >> 1);
        long src = ((long)e * N13 + r) * (HDIM/4) + kb;
        g_w13[i] = (uint8_t)ldb(w13p, src, s_mode);
    } else if (bid < RW13_BLKS + RW2_BLKS) {
        if (tid == 0) s_mode = detect_mode(w2p, 0);
        __syncthreads();
        long i = (long)(bid - RW13_BLKS) * 256 + tid;
        g_w2[i] = (uint8_t)ldb(w2p, i, s_mode);
    } else if (bid < RW13_BLKS + RW2_BLKS + RA13_BLKS) {
        if (tid == 0) s_mode = detect_mode(a13q, 1);
        __syncthreads();
        int i = (bid - RW13_BLKS - RW2_BLKS) * 256 + tid;
        g_a13f[i] = (float)ldq(a13q, i, s_mode) * a13s[0];
    } else if (bid < RW13_BLKS + RW2_BLKS + RA13_BLKS + RA2_BLKS) {
        if (tid == 0) s_mode = detect_mode(a2q, 1);
        __syncthreads();
        int i = (bid - RW13_BLKS - RW2_BLKS - RA13_BLKS) * 256 + tid;
        g_a2f[i] = (float)ldq(a2q, i, s_mode) * a2s[0];
    } else {
        int row = bid - (RW13_BLKS + RW2_BLKS + RA13_BLKS + RA2_BLKS);
        ((uint4*)g_xs)[(size_t)row * 256 + tid] = make_uint4(0, 0, 0, 0);
    }
}

// ---------------- single-block routing: router + scan + assign ----------------
__global__ __launch_bounds__(1024) void k_route(const float* __restrict__ logits) {
    __shared__ int s_cnt[NEXP];
    __shared__ int s_off[NEXP];
    int tid = threadIdx.x;
    if (tid < NEXP) s_cnt[tid] = 0;
    __syncthreads();

    int li0[4], li1[4];
    for (int it = 0; it < 4; it++) {
        int t = tid + it * 1024;
        float l[NEXP];
#pragma unroll
        for (int e = 0; e < NEXP; e++) l[e] = logits[t * NEXP + e];
        int i0 = 0; float b0 = l[0];
#pragma unroll
        for (int e = 1; e < NEXP; e++) if (l[e] > b0) { b0 = l[e]; i0 = e; }
        int i1 = -1; float b1 = -1e30f;
#pragma unroll
        for (int e = 0; e < NEXP; e++) if (e != i0 && l[e] > b1) { b1 = l[e]; i1 = e; }
        float w0 = 1.0f / (1.0f + expf(b1 - b0));
        g_token_eidx[2*t]   = i0;
        g_token_eidx[2*t+1] = i1;
        g_token_wt[2*t]     = w0;
        g_token_wt[2*t+1]   = 1.0f - w0;
        atomicAdd(&s_cnt[i0], 1);
        atomicAdd(&s_cnt[i1], 1);
        li0[it] = i0; li1[it] = i1;
    }
    __syncthreads();
    if (tid == 0) {
        int off = 0, tiles = 0;
        for (int e = 0; e < NEXP; e++) {
            g_pad_off[e] = off; s_off[e] = off;
            int nt = (s_cnt[e] + 127) >> 7;
            for (int j = 0; j < nt; j++) { g_tile_e[tiles] = e; g_tile_m0[tiles] = off + (j << 7); tiles++; }
            off += nt << 7;
        }
        g_pad_off[NEXP] = off;
        g_ntiles = tiles;
        g_nslots = off;
    }
    __syncthreads();
    if (tid < NEXP) s_cnt[tid] = 0;
    __syncthreads();
    for (int it = 0; it < 4; it++) {
        int t = tid + it * 1024;
        int r0 = atomicAdd(&s_cnt[li0[it]], 1);
        g_token_slot[2*t]   = s_off[li0[it]] + r0;
        int r1 = atomicAdd(&s_cnt[li1[it]], 1);
        g_token_slot[2*t+1] = s_off[li1[it]] + r1;
    }
}

// xs[slot(r)][h] = fp16( x[t][h] * a13f[e][h] ), r = 2t+k;  pad rows pre-zeroed
__global__ void k_xs(const float* __restrict__ x) {
    int r = blockIdx.x;
    int t = r >> 1;
    int slot = g_token_slot[r];
    int e = g_token_eidx[r];
    const float* xr = x + (size_t)t * HDIM;
    const float* ar = g_a13f + (size_t)e * HDIM;
    __half* o = g_xs + (size_t)slot * HDIM;
    for (int j = threadIdx.x; j < HDIM; j += 256)
        o[j] = __float2half(xr[j] * ar[j]);
}

__global__ void k_combine(float* __restrict__ out) {
    int t = blockIdx.x;
    int s0 = g_token_slot[2*t], s1 = g_token_slot[2*t+1];
    float w0 = g_token_wt[2*t], w1 = g_token_wt[2*t+1];
    const float* d0 = g_down + (size_t)s0 * HDIM;
    const float* d1 = g_down + (size_t)s1 * HDIM;
    float* o = out + (size_t)t * HDIM;
    for (int j = threadIdx.x; j < HDIM; j += 256)
        o[j] = w0 * d0[j] + w1 * d1[j];
}

// ---------------- GEMM: fp16 A x ternary-2bit B, fused silu epilogue ----------
__device__ __forceinline__ void ldsm4(uint32_t& r0, uint32_t& r1, uint32_t& r2, uint32_t& r3,
                                      const void* p) {
    uint32_t a = (uint32_t)__cvta_generic_to_shared(p);
    asm volatile("ldmatrix.sync.aligned.m8n8.x4.shared.b16 {%0,%1,%2,%3},[%4];"
                 : "=r"(r0), "=r"(r1), "=r"(r2), "=r"(r3) : "r"(a));
}
__device__ __forceinline__ void mma16816(float* c, const uint32_t* a, const uint32_t* b) {
    asm volatile("mma.sync.aligned.m16n8k16.row.col.f32.f16.f16.f32 "
                 "{%0,%1,%2,%3},{%4,%5,%6,%7},{%8,%9},{%0,%1,%2,%3};"
                 : "+f"(c[0]), "+f"(c[1]), "+f"(c[2]), "+f"(c[3])
                 : "r"(a[0]), "r"(a[1]), "r"(a[2]), "r"(a[3]), "r"(b[0]), "r"(b[1]));
}
__device__ __forceinline__ float silu_f(float g) { return g / (1.0f + expf(-g)); }

template <int WHICH>  // 0: xs @ w13i^T -> silu-fused -> g_act.  1: act @ w2^T -> g_down.
__global__ __launch_bounds__(256, 2) void k_gemm() {
    constexpr int K = (WHICH == 0) ? HDIM : IDIM;
    constexpr int N = (WHICH == 0) ? N13  : HDIM;
    constexpr int KB = K / 4;
    constexpr int S  = K / 32;
    const __half*  A  = (WHICH == 0) ? g_xs  : g_act;
    const uint8_t* Bp = (WHICH == 0) ? g_w13 : g_w2;

    __shared__ __half sA[2][128][40];
    __shared__ __half sB[2][128][40];
    __shared__ uint2  s_lut[256];

    int bx = blockIdx.x;
    if (bx >= g_ntiles) return;
    int e  = g_tile_e[bx];
    int m0 = g_tile_m0[bx];
    int n0 = blockIdx.y * 128;
    const uint8_t* Be = Bp + (size_t)e * N * KB;

    int tid = threadIdx.x;
    {
        int b = tid;
        unsigned short h[4];
#pragma unroll
        for (int j = 0; j < 4; j++) {
            int v = ((b >> (2*j)) & 3) - 1;
            h[j] = (v == 0) ? 0x0000 : ((v == 1) ? 0x3C00 : 0xBC00);
        }
        uint2 val;
        val.x = (uint32_t)h[0] | ((uint32_t)h[1] << 16);
        val.y = (uint32_t)h[2] | ((uint32_t)h[3] << 16);
        s_lut[tid] = val;
    }

    int w = tid >> 5, lane = tid & 31;
    int wm = w & 3, wn = w >> 2;
    int gid = lane >> 2, tig = lane & 3;
    int aRow = (lane & 7) + ((lane >> 3) & 1) * 8;
    int aCol = ((lane >> 4) & 1) * 8;
    int bRow = (lane & 7) + ((lane >> 4) & 1) * 8;
    int bCol = ((lane >> 3) & 1) * 8;

    int ar0 = tid >> 2, ac0 = tid & 3;
    int br  = tid >> 1, bsel = tid & 1;
    const __half* Abase = A + (size_t)m0 * K;

    uint32_t pk = 0;
    {
#pragma unroll
        for (int i = 0; i < 2; i++) {
            int r = ar0 + i * 64;
            uint32_t dst = (uint32_t)__cvta_generic_to_shared(&sA[0][r][ac0 * 8]);
            const void* src = Abase + (size_t)r * K + ac0 * 8;
            asm volatile("cp.async.cg.shared.global [%0], [%1], 16;" :: "r"(dst), "l"(src));
        }
        asm volatile("cp.async.commit_group;");
        pk = *(const uint32_t*)(Be + (size_t)(n0 + br) * KB + bsel * 4);
    }
    __syncthreads();
    {
#pragma unroll
        for (int j = 0; j < 4; j++)
            *(uint2*)(&sB[0][br][bsel * 16 + j * 4]) = s_lut[(pk >> (8 * j)) & 0xFF];
    }
    asm volatile("cp.async.wait_group 0;");
    __syncthreads();

    float c[2][8][4] = {};

    for (int s = 0; s < S; s++) {
        int cur = s & 1, nxt = cur ^ 1;
        if (s + 1 < S) {
            int k0 = (s + 1) * 32;
#pragma unroll
            for (int i = 0; i < 2; i++) {
                int r = ar0 + i * 64;
                uint32_t dst = (uint32_t)__cvta_generic_to_shared(&sA[nxt][r][ac0 * 8]);
                const void* src = Abase + (size_t)r * K + k0 + ac0 * 8;
                asm volatile("cp.async.cg.shared.global [%0], [%1], 16;" :: "r"(dst), "l"(src));
            }
            asm volatile("cp.async.commit_group;");
            pk = *(const uint32_t*)(Be + (size_t)(n0 + br) * KB + (k0 >> 2) + bsel * 4);
        }

#pragma unroll
        for (int kk = 0; kk < 32; kk += 16) {
            uint32_t af[2][4], bf[8][2];
#pragma unroll
            for (int mt = 0; mt < 2; mt++)
                ldsm4(af[mt][0], af[mt][1], af[mt][2], af[mt][3],
                      &sA[cur][wm * 32 + mt * 16 + aRow][kk + aCol]);
#pragma unroll
            for (int np = 0; np < 4; np++) {
                uint32_t r0, r1, r2, r3;
                ldsm4(r0, r1, r2, r3, &sB[cur][wn * 64 + np * 16 + bRow][kk + bCol]);
                bf[2*np][0]   = r0; bf[2*np][1]   = r1;
                bf[2*np+1][0] = r2; bf[2*np+1][1] = r3;
            }
#pragma unroll
            for (int mt = 0; mt < 2; mt++)
#pragma unroll
                for (int ns = 0; ns < 8; ns++)
                    mma16816(c[mt][ns], af[mt], bf[ns]);
        }

        if (s + 1 < S) {
            asm volatile("cp.async.wait_group 0;");
#pragma unroll
            for (int j = 0; j < 4; j++)
                *(uint2*)(&sB[nxt][br][bsel * 16 + j * 4]) = s_lut[(pk >> (8 * j)) & 0xFF];
        }
        __syncthreads();
    }

    if (WHICH == 0) {
        // interleaved cols: even=gate_j, odd=up_j; each thread's float2 is the pair
#pragma unroll
        for (int mt = 0; mt < 2; mt++)
#pragma unroll
            for (int ns = 0; ns < 8; ns++) {
                int col = n0 + wn * 64 + ns * 8 + tig * 2;
                int j = col >> 1;
                float al = __ldg(&g_a2f[(size_t)e * IDIM + j]);
                int row0 = m0 + wm * 32 + mt * 16 + gid;
                g_act[(size_t)row0 * IDIM + j] =
                    __float2half(silu_f(c[mt][ns][0]) * c[mt][ns][1] * al);
                g_act[(size_t)(row0 + 8) * IDIM + j] =
                    __float2half(silu_f(c[mt][ns][2]) * c[mt][ns][3] * al);
            }
    } else {
#pragma unroll
        for (int mt = 0; mt < 2; mt++)
#pragma unroll
            for (int ns = 0; ns < 8; ns++) {
                int row = m0 + wm * 32 + mt * 16 + gid;
                int col = n0 + wn * 64 + ns * 8 + tig * 2;
                *(float2*)(g_down + (size_t)row * N + col)       = make_float2(c[mt][ns][0], c[mt][ns][1]);
                *(float2*)(g_down + (size_t)(row + 8) * N + col) = make_float2(c[mt][ns][2], c[mt][ns][3]);
            }
    }
}

// ---------------- launch ------------------------------------------------------
extern "C" void kernel_launch(void* const* d_in, const int* in_sizes, int n_in,
                              void* d_out, int out_size) {
    const float* x      = nullptr;
    const float* logits = nullptr;
    const void*  w13p   = nullptr;
    const void*  a13q   = nullptr;
    const float* a13s   = nullptr;
    const void*  w2p    = nullptr;
    const void*  a2q    = nullptr;
    const float* a2s    = nullptr;
    for (int i = 0; i < n_in; i++) {
        long sz = in_sizes[i];
        void* p = d_in[i];
        if      (sz == 8388608)  x      = (const float*)p;
        else if (sz == 65536)    logits = (const float*)p;
        else if (sz == 12582912) w13p   = p;
        else if (sz == 32768)    a13q   = p;
        else if (sz == 6291456)  w2p    = p;
        else if (sz == 12288)    a2q    = p;
        else if (sz == 1) { if (!a13s) a13s = (const float*)p; else a2s = (const float*)p; }
    }
    float* out = (float*)d_out;

    k_repack <<<REPACK_BLKS, 256>>>(w13p, w2p, a13q, a13s, a2q, a2s);  // 0
    k_route  <<<1, 1024>>>(logits);                                     // 1
    k_xs     <<<T_TOK*2, 256>>>(x);                                     // 2
    k_gemm<0><<<dim3(GRID_TILES, N13 / 128), 256>>>();                  // 3  <- ncu lands here
    k_gemm<1><<<dim3(GRID_TILES, HDIM / 128), 256>>>();                 // 4
    k_combine<<<T_TOK, 256>>>(out);                                     // 5
}